// round 6
// baseline (speedup 1.0000x reference)
#include <cuda_runtime.h>
#include <cstdint>

// ---------------------------------------------------------------------------
// GCN layer: out = relu( D_in^-1/2 · A · D_out^-1/2 · (X @ W) + b )
// N=100000, E=1600000, IN=256, OUT=32  (fp32, src/dst int32)
//
// Graph (two independent chains, join at agg):
//   side: memset(outdeg) -> deg_src -> gemm ------------+
//   main: memset(indeg,ctr) -> deg_dst -> scan -> fill -+-> agg
// ---------------------------------------------------------------------------

#define NMAX 100000
#define EMAX 1600000
#define IN_F 256
#define OUT_F 32
#define SCAN_BLK 512
#define SCAN_SHIFT 9
#define SCAN_NBLK ((NMAX + SCAN_BLK - 1) / SCAN_BLK)   // 196

#define TILE_R 64
#define FP_STRIDE 33
#define GEMM_SMEM (IN_F * OUT_F * 4 + IN_F * FP_STRIDE * 8)   // 98KB

__device__ unsigned g_outdeg[NMAX];
__device__ unsigned g_indeg[NMAX];
__device__ unsigned g_off[NMAX];
__device__ unsigned g_bsum[SCAN_NBLK];
__device__ unsigned g_scan_ctr;
__device__ int      g_esrc[EMAX];
__device__ __align__(16) float g_h[(size_t)NMAX * OUT_F];

// packed f32x2 helpers -------------------------------------------------------
#define FMA_F32X2(acc, a, b) \
    asm("fma.rn.f32x2 %0, %1, %2, %0;" : "+l"(acc) : "l"(a), "l"(b))
#define PACK_DUP_F32X2(out, w) \
    asm("mov.b64 %0, {%1, %1};" : "=l"(out) : "f"(w))
#define UNPACK_F32X2(lo, hi, in) \
    asm("mov.b64 {%0, %1}, %2;" : "=f"(lo), "=f"(hi) : "l"(in))

// ---------------------------------------------------------------------------
// Degree kernels: 4 edges per thread via int4 loads, REDG (no return).
__global__ void k_deg_src(const int* __restrict__ src, int E) {
    int i = blockIdx.x * blockDim.x + threadIdx.x;
    int base = i * 4;
    if (base + 3 < E) {
        int4 v = ((const int4*)src)[i];
        atomicAdd(&g_outdeg[v.x], 1u);
        atomicAdd(&g_outdeg[v.y], 1u);
        atomicAdd(&g_outdeg[v.z], 1u);
        atomicAdd(&g_outdeg[v.w], 1u);
    } else {
        for (int j = base; j < E; ++j) atomicAdd(&g_outdeg[src[j]], 1u);
    }
}

__global__ void k_deg_dst(const int* __restrict__ dst, int E) {
    int i = blockIdx.x * blockDim.x + threadIdx.x;
    int base = i * 4;
    if (base + 3 < E) {
        int4 v = ((const int4*)dst)[i];
        atomicAdd(&g_indeg[v.x], 1u);
        atomicAdd(&g_indeg[v.y], 1u);
        atomicAdd(&g_indeg[v.z], 1u);
        atomicAdd(&g_indeg[v.w], 1u);
    } else {
        for (int j = base; j < E; ++j) atomicAdd(&g_indeg[dst[j]], 1u);
    }
}

// ---------------------------------------------------------------------------
// Single-pass two-level scan (last-block aggregates g_bsum).
__global__ void k_scan(int n_nodes) {
    __shared__ unsigned s[SCAN_BLK];
    __shared__ bool is_last;
    int t = threadIdx.x;
    int i = blockIdx.x * SCAN_BLK + t;
    unsigned v = (i < n_nodes) ? g_indeg[i] : 0u;
    s[t] = v;
    __syncthreads();
    for (int off = 1; off < SCAN_BLK; off <<= 1) {
        unsigned x = (t >= off) ? s[t - off] : 0u;
        __syncthreads();
        s[t] += x;
        __syncthreads();
    }
    if (i < n_nodes) g_off[i] = s[t] - v;          // block-local exclusive
    if (t == SCAN_BLK - 1) g_bsum[blockIdx.x] = s[t];

    __threadfence();
    if (t == 0) {
        unsigned done = atomicAdd(&g_scan_ctr, 1u);
        is_last = (done == (unsigned)(gridDim.x - 1));
    }
    __syncthreads();
    if (is_last) {
        __threadfence();
        unsigned bv = (t < SCAN_NBLK) ? g_bsum[t] : 0u;
        s[t] = bv;
        __syncthreads();
        for (int off = 1; off < 256; off <<= 1) {
            unsigned x = (t >= off && t < 256) ? s[t - off] : 0u;
            __syncthreads();
            if (t < 256) s[t] += x;
            __syncthreads();
        }
        if (t < SCAN_NBLK) g_bsum[t] = s[t] - bv;  // exclusive block sums
    }
}

// ---------------------------------------------------------------------------
// CSR fill: cursor fused into g_off (atomic bump).
__global__ void k_fill(const int* __restrict__ src,
                       const int* __restrict__ dst, int E) {
    int i = blockIdx.x * blockDim.x + threadIdx.x;
    if (i < E) {
        int d = dst[i];
        unsigned pos = atomicAdd(&g_off[d], 1u) + g_bsum[d >> SCAN_SHIFT];
        g_esrc[pos] = src[i];
    }
}

// ---------------------------------------------------------------------------
// GEMM with packed f32x2 FMA. 256 threads, 64-row tile, 98KB dynamic smem.
__global__ void __launch_bounds__(256, 2)
k_gemm(const float* __restrict__ feat, const float* __restrict__ W,
       int n_nodes) {
    extern __shared__ float smem[];
    float* sW = smem;                                    // [256][32]
    float* sFPf = smem + IN_F * OUT_F;                   // [256 k][66 floats]
    unsigned long long* sFPu = (unsigned long long*)sFPf;

    const int tid  = threadIdx.x;
    const int lane = tid & 31;
    const int warp = tid >> 5;
    const int row0 = blockIdx.x * TILE_R;

    for (int i = tid; i < (IN_F * OUT_F) / 4; i += 256)
        ((float4*)sW)[i] = ((const float4*)W)[i];

    // transpose-load feat tile (coalesced LDG.32, 2-way-conflict STS)
    for (int it = 0; it < TILE_R; ++it) {
        int idx = tid + 256 * it;          // idx = r_local*256 + k
        int rl = idx >> 8;
        int k  = idx & 255;
        int row = row0 + rl;
        float v = (row < n_nodes) ? feat[(size_t)row * IN_F + k] : 0.f;
        sFPf[k * (2 * FP_STRIDE) + rl] = v;
    }
    __syncthreads();

    unsigned long long acc[4];
    acc[0] = acc[1] = acc[2] = acc[3] = 0ull;
    const int pbase = warp * 4;                 // 4 row-pairs per warp

    for (int kc = 0; kc < IN_F / 32; ++kc) {
        unsigned long long w2[32];
        #pragma unroll
        for (int kk = 0; kk < 32; ++kk) {
            float w = sW[(kc * 32 + kk) * OUT_F + lane];
            PACK_DUP_F32X2(w2[kk], w);
        }
        #pragma unroll
        for (int rp = 0; rp < 4; ++rp) {
            const unsigned long long* f = &sFPu[(size_t)(kc * 32) * FP_STRIDE
                                                + pbase + rp];
            #pragma unroll
            for (int kk = 0; kk < 32; ++kk) {
                unsigned long long f2 = f[kk * FP_STRIDE];   // LDS.b64 bcast
                FMA_F32X2(acc[rp], f2, w2[kk]);
            }
        }
    }

    #pragma unroll
    for (int rp = 0; rp < 4; ++rp) {
        float a0, a1;
        UNPACK_F32X2(a0, a1, acc[rp]);
        int r0 = row0 + (pbase + rp) * 2;
        if (r0 < n_nodes) {
            unsigned d = g_outdeg[r0];
            g_h[(size_t)r0 * OUT_F + lane] = a0 * rsqrtf((float)(d ? d : 1u));
        }
        if (r0 + 1 < n_nodes) {
            unsigned d = g_outdeg[r0 + 1];
            g_h[(size_t)(r0 + 1) * OUT_F + lane] =
                a1 * rsqrtf((float)(d ? d : 1u));
        }
    }
}

// ---------------------------------------------------------------------------
// Aggregation: warp per destination node, lane = output column.
__global__ void k_agg(float* __restrict__ out,
                      const float* __restrict__ bias, int n_nodes) {
    int warp = (blockIdx.x * blockDim.x + threadIdx.x) >> 5;
    int lane = threadIdx.x & 31;
    if (warp >= n_nodes) return;

    unsigned deg = g_indeg[warp];
    unsigned off = g_off[warp] + g_bsum[warp >> SCAN_SHIFT] - deg;

    float acc0 = 0.f, acc1 = 0.f;
    for (unsigned c = 0; c < deg; c += 32) {
        unsigned rem = deg - c;
        unsigned cnt = rem < 32u ? rem : 32u;
        int e = (lane < cnt) ? g_esrc[off + c + lane] : 0;
        unsigned j = 0;
        for (; j + 2 <= cnt; j += 2) {
            int s0 = __shfl_sync(0xFFFFFFFFu, e, j);
            int s1 = __shfl_sync(0xFFFFFFFFu, e, j + 1);
            acc0 += g_h[(size_t)s0 * OUT_F + lane];
            acc1 += g_h[(size_t)s1 * OUT_F + lane];
        }
        if (j < cnt) {
            int s0 = __shfl_sync(0xFFFFFFFFu, e, j);
            acc0 += g_h[(size_t)s0 * OUT_F + lane];
        }
    }

    float sc = rsqrtf((float)(deg ? deg : 1u));
    float v = fmaf(acc0 + acc1, sc, bias[lane]);
    out[(size_t)warp * OUT_F + lane] = fmaxf(v, 0.f);
}

// ---------------------------------------------------------------------------
extern "C" void kernel_launch(void* const* d_in, const int* in_sizes, int n_in,
                              void* d_out, int out_size) {
    const float* feat = (const float*)d_in[0];
    const int*   src  = (const int*)d_in[1];
    const int*   dst  = (const int*)d_in[2];
    const float* W    = (const float*)d_in[3];
    const float* bias = (const float*)d_in[4];
    float* out = (float*)d_out;

    const int N = in_sizes[0] / IN_F;
    const int E = in_sizes[1];
    const int nth4 = (E + 3) / 4;

    cudaFuncSetAttribute(k_gemm, cudaFuncAttributeMaxDynamicSharedMemorySize,
                         GEMM_SMEM);

    void *p_outdeg, *p_indeg, *p_ctr;
    cudaGetSymbolAddress(&p_outdeg, g_outdeg);
    cudaGetSymbolAddress(&p_indeg, g_indeg);
    cudaGetSymbolAddress(&p_ctr, g_scan_ctr);

    // host-only objects (no device memory)
    cudaStream_t side;
    cudaEvent_t ev_fork, ev_join;
    cudaStreamCreateWithFlags(&side, cudaStreamNonBlocking);
    cudaEventCreateWithFlags(&ev_fork, cudaEventDisableTiming);
    cudaEventCreateWithFlags(&ev_join, cudaEventDisableTiming);

    // fork side chain from the very start
    cudaEventRecord(ev_fork, 0);
    cudaStreamWaitEvent(side, ev_fork, 0);

    // side chain: outdeg -> deg_src -> gemm
    cudaMemsetAsync(p_outdeg, 0, (size_t)N * 4, side);
    k_deg_src<<<(nth4 + 255) / 256, 256, 0, side>>>(src, E);
    k_gemm<<<(N + TILE_R - 1) / TILE_R, 256, GEMM_SMEM, side>>>(feat, W, N);
    cudaEventRecord(ev_join, side);

    // main chain: indeg,ctr -> deg_dst -> scan -> fill
    cudaMemsetAsync(p_indeg, 0, (size_t)N * 4, 0);
    cudaMemsetAsync(p_ctr, 0, 4, 0);
    k_deg_dst<<<(nth4 + 255) / 256, 256>>>(dst, E);
    k_scan<<<SCAN_NBLK, SCAN_BLK>>>(N);
    k_fill<<<(E + 255) / 256, 256>>>(src, dst, E);

    // join, then aggregate
    cudaStreamWaitEvent(0, ev_join, 0);
    k_agg<<<(N * 32 + 255) / 256, 256>>>(out, bias, N);
}